// round 2
// baseline (speedup 1.0000x reference)
#include <cuda_runtime.h>
#include <math.h>

#define BATCH  4
#define CDIM   192
#define NHEADS 8
#define HDIM   24
#define HWN    65536
#define OC3    576   // 3*CDIM

typedef unsigned long long u64;

// ---- scratch (device globals; no allocation allowed) ----
__device__ float g_qkv [(size_t)BATCH * OC3 * HWN];   // qkv after 1x1 conv
__device__ float g_conv[(size_t)BATCH * OC3 * HWN];   // after depthwise 3x3
__device__ float g_gram[BATCH * NHEADS * 624];        // 576 gram + 24 |q|^2 + 24 |k|^2
__device__ float g_M   [BATCH * CDIM * CDIM];         // fused proj @ attn matrices

__device__ __forceinline__ u64 ffma2(u64 a, u64 b, u64 c) {
    u64 d;
    asm("fma.rn.f32x2 %0, %1, %2, %3;" : "=l"(d) : "l"(a), "l"(b), "l"(c));
    return d;
}

// ============================================================
// K1/K5: C[b][m][n] = sum_k A[b][m][k] * B[b][k][n], N = 65536
// BM=64, BN=128, BK=16, 256 threads, 8x4 microtile via f32x2 FFMA2.
// A duplicated in smem as {a,a} u64 pairs -> broadcast loads, no packing.
// ============================================================
__global__ __launch_bounds__(256) void gemm_kernel(
    const float* __restrict__ A, size_t aStride,
    const float* __restrict__ Bm, size_t bStride,
    float* __restrict__ Cm, size_t cStride, int K)
{
    __shared__ alignas(16) u64   As2[16][66];    // [k][m] dup pairs, row 528B (16B aligned)
    __shared__ alignas(16) float Bs[16][128];

    int bz = blockIdx.z;
    const float* Ab = A  + (size_t)bz * aStride;
    const float* Bb = Bm + (size_t)bz * bStride;
    float*       Cb = Cm + (size_t)bz * cStride;

    int m0 = blockIdx.y * 64;
    int n0 = blockIdx.x * 128;
    int tid = threadIdx.x;
    int tm0 = (tid >> 5) * 8;    // warp id -> m offset (warp-uniform A)
    int tn0 = (tid & 31) * 4;
    int am  = tid >> 2;          // A tile: 64 rows x 16 k, float4 per thread
    int ak  = (tid & 3) * 4;
    int br  = tid >> 5;          // B tile rows br, br+8
    int bc  = (tid & 31) * 4;

    u64 acc[8][2];
#pragma unroll
    for (int i = 0; i < 8; i++) { acc[i][0] = 0ull; acc[i][1] = 0ull; }

    for (int k0 = 0; k0 < K; k0 += 16) {
        float4 av = *(const float4*)&Ab[(size_t)(m0 + am) * K + k0 + ak];
        float4 b0 = *(const float4*)&Bb[(size_t)(k0 + br) * HWN + n0 + bc];
        float4 b1 = *(const float4*)&Bb[(size_t)(k0 + br + 8) * HWN + n0 + bc];
        __syncthreads();
        {
            float va[4] = {av.x, av.y, av.z, av.w};
#pragma unroll
            for (int i = 0; i < 4; i++) {
                float2 dup = make_float2(va[i], va[i]);
                As2[ak + i][am] = *(u64*)&dup;
            }
        }
        *(float4*)&Bs[br][bc]     = b0;
        *(float4*)&Bs[br + 8][bc] = b1;
        __syncthreads();
#pragma unroll
        for (int k = 0; k < 16; k++) {
            const u64* arow = &As2[k][tm0];
            u64 a0 = arow[0], a1 = arow[1], a2 = arow[2], a3 = arow[3];
            u64 a4 = arow[4], a5 = arow[5], a6 = arow[6], a7 = arow[7];
            const u64* brow = (const u64*)&Bs[k][tn0];
            u64 bv0 = brow[0], bv1 = brow[1];
            acc[0][0] = ffma2(a0, bv0, acc[0][0]); acc[0][1] = ffma2(a0, bv1, acc[0][1]);
            acc[1][0] = ffma2(a1, bv0, acc[1][0]); acc[1][1] = ffma2(a1, bv1, acc[1][1]);
            acc[2][0] = ffma2(a2, bv0, acc[2][0]); acc[2][1] = ffma2(a2, bv1, acc[2][1]);
            acc[3][0] = ffma2(a3, bv0, acc[3][0]); acc[3][1] = ffma2(a3, bv1, acc[3][1]);
            acc[4][0] = ffma2(a4, bv0, acc[4][0]); acc[4][1] = ffma2(a4, bv1, acc[4][1]);
            acc[5][0] = ffma2(a5, bv0, acc[5][0]); acc[5][1] = ffma2(a5, bv1, acc[5][1]);
            acc[6][0] = ffma2(a6, bv0, acc[6][0]); acc[6][1] = ffma2(a6, bv1, acc[6][1]);
            acc[7][0] = ffma2(a7, bv0, acc[7][0]); acc[7][1] = ffma2(a7, bv1, acc[7][1]);
        }
    }
#pragma unroll
    for (int i = 0; i < 8; i++) {
        ulonglong2 o;
        o.x = acc[i][0]; o.y = acc[i][1];
        *(ulonglong2*)&Cb[(size_t)(m0 + tm0 + i) * HWN + n0 + tn0] = o;
    }
}

// ============================================================
// K2: depthwise 3x3, pad=1. Each thread: 4 consecutive x pixels.
// ============================================================
__global__ __launch_bounds__(256) void dwconv_kernel(
    const float* __restrict__ in, const float* __restrict__ wAll,
    float* __restrict__ out)
{
    int idx = blockIdx.x * 256 + threadIdx.x;
    int p4 = idx & 16383;
    int bc = idx >> 14;
    int ch = bc % OC3;
    int y  = p4 >> 6;
    int x0 = (p4 & 63) << 2;
    const float* base = in + (size_t)bc * HWN;

    float w[9];
#pragma unroll
    for (int i = 0; i < 9; i++) w[i] = __ldg(&wAll[ch * 9 + i]);

    float s0 = 0.f, s1 = 0.f, s2 = 0.f, s3 = 0.f;
#pragma unroll
    for (int ky = 0; ky < 3; ky++) {
        int yy = y + ky - 1;
        if ((unsigned)yy >= 256u) continue;
        const float* row = base + yy * 256;
        float4 v    = *(const float4*)&row[x0];
        float left  = (x0 > 0)   ? row[x0 - 1] : 0.f;
        float right = (x0 < 252) ? row[x0 + 4] : 0.f;
        float w0 = w[ky * 3], w1 = w[ky * 3 + 1], w2 = w[ky * 3 + 2];
        s0 += left * w0 + v.x  * w1 + v.y  * w2;
        s1 += v.x  * w0 + v.y  * w1 + v.z  * w2;
        s2 += v.y  * w0 + v.z  * w1 + v.w  * w2;
        s3 += v.z  * w0 + v.w  * w1 + right * w2;
    }
    float4 o = {s0, s1, s2, s3};
    *(float4*)&out[(size_t)idx * 4] = o;
}

// ============================================================
__global__ void zero_gram() {
    int i = blockIdx.x * blockDim.x + threadIdx.x;
    if (i < BATCH * NHEADS * 624) g_gram[i] = 0.f;
}

// ============================================================
// K3: gram. Register-tiled 3x3 per thread: 8x8 (d,e) positions x 4 n-slices.
// Each block handles nPer=1024 pixels of one (b,h); atomicAdd partials.
// ============================================================
__global__ __launch_bounds__(256) void gram_kernel(const float* __restrict__ conv)
{
    __shared__ float qs[24][68];
    __shared__ float ks[24][68];
    int bh = blockIdx.y;
    int b = bh >> 3, hh = bh & 7;
    const float* qb = conv + ((size_t)b * OC3 + hh * HDIM) * HWN;
    const float* kb = conv + ((size_t)b * OC3 + CDIM + hh * HDIM) * HWN;

    int t = threadIdx.x;
    int slice = t >> 6;           // 0..3 -> n sub-range within 64-tile
    int p = t & 63;               // 0..63 position
    int ty = p >> 3, tx = p & 7;
    int d0 = ty * 3, e0 = tx * 3;
    int ns = slice * 16;

    float a00=0,a01=0,a02=0,a10=0,a11=0,a12=0,a20=0,a21=0,a22=0;
    float nacc = 0.f;

    int nStart = blockIdx.x * 1024;
#pragma unroll 1
    for (int n0 = nStart; n0 < nStart + 1024; n0 += 64) {
        __syncthreads();
        for (int i = t; i < 24 * 16; i += 256) {
            int r = i >> 4, c4 = (i & 15) << 2;
            *(float4*)&qs[r][c4] = *(const float4*)&qb[(size_t)r * HWN + n0 + c4];
            *(float4*)&ks[r][c4] = *(const float4*)&kb[(size_t)r * HWN + n0 + c4];
        }
        __syncthreads();
#pragma unroll
        for (int n = 0; n < 16; n++) {
            int nn = ns + n;
            float q0 = qs[d0][nn], q1 = qs[d0+1][nn], q2 = qs[d0+2][nn];
            float k0 = ks[e0][nn], k1 = ks[e0+1][nn], k2 = ks[e0+2][nn];
            a00 += q0*k0; a01 += q0*k1; a02 += q0*k2;
            a10 += q1*k0; a11 += q1*k1; a12 += q1*k2;
            a20 += q2*k0; a21 += q2*k1; a22 += q2*k2;
        }
        if (p < 48) {
            const float* row = (p < 24) ? qs[p] : ks[p - 24];
#pragma unroll
            for (int n = 0; n < 16; n++) { float v = row[ns + n]; nacc += v * v; }
        }
    }
    float* gb = &g_gram[bh * 624];
    atomicAdd(&gb[(d0+0)*24 + e0+0], a00); atomicAdd(&gb[(d0+0)*24 + e0+1], a01); atomicAdd(&gb[(d0+0)*24 + e0+2], a02);
    atomicAdd(&gb[(d0+1)*24 + e0+0], a10); atomicAdd(&gb[(d0+1)*24 + e0+1], a11); atomicAdd(&gb[(d0+1)*24 + e0+2], a12);
    atomicAdd(&gb[(d0+2)*24 + e0+0], a20); atomicAdd(&gb[(d0+2)*24 + e0+1], a21); atomicAdd(&gb[(d0+2)*24 + e0+2], a22);
    if (p < 48) atomicAdd(&gb[576 + p], nacc);
}

// ============================================================
// K4: normalize gram -> softmax -> fuse with proj: M_b = proj @ blockdiag(attn)
// ============================================================
__global__ __launch_bounds__(256) void attn_proj_kernel(
    const float* __restrict__ projw, const float* __restrict__ temp)
{
    __shared__ float attn_s[NHEADS * HDIM * HDIM];
    int b = blockIdx.x;
    int t = threadIdx.x;
    if (t < CDIM) {
        int hh = t / HDIM, d = t % HDIM;
        const float* G = &g_gram[(b * NHEADS + hh) * 624];
        float nq = fmaxf(sqrtf(G[576 + d]), 1e-12f);
        float tm = temp[hh];
        float row[HDIM];
        float mx = -1e30f;
#pragma unroll
        for (int e = 0; e < HDIM; e++) {
            float nk = fmaxf(sqrtf(G[600 + e]), 1e-12f);
            float a = G[d * 24 + e] / (nq * nk) * tm;
            row[e] = a; mx = fmaxf(mx, a);
        }
        float s = 0.f;
#pragma unroll
        for (int e = 0; e < HDIM; e++) { row[e] = expf(row[e] - mx); s += row[e]; }
        float inv = 1.f / s;
#pragma unroll
        for (int e = 0; e < HDIM; e++) attn_s[hh * 576 + d * 24 + e] = row[e] * inv;
    }
    __syncthreads();
    if (t < CDIM) {
        int o = t;
        const float* pr = &projw[o * CDIM];
        for (int hh = 0; hh < NHEADS; hh++) {
#pragma unroll
            for (int e = 0; e < HDIM; e++) {
                float acc = 0.f;
#pragma unroll
                for (int d = 0; d < HDIM; d++)
                    acc += pr[hh * 24 + d] * attn_s[hh * 576 + d * 24 + e];
                g_M[((size_t)b * CDIM + o) * CDIM + hh * 24 + e] = acc;
            }
        }
    }
}

// ============================================================
extern "C" void kernel_launch(void* const* d_in, const int* in_sizes, int n_in,
                              void* d_out, int out_size)
{
    const float* x      = (const float*)d_in[0];
    const float* qkv_w  = (const float*)d_in[1];
    const float* dw_w   = (const float*)d_in[2];
    const float* proj_w = (const float*)d_in[3];
    const float* temp   = (const float*)d_in[4];
    float* out = (float*)d_out;

    float *qkv, *convp, *Mp;
    cudaGetSymbolAddress((void**)&qkv,   g_qkv);
    cudaGetSymbolAddress((void**)&convp, g_conv);
    cudaGetSymbolAddress((void**)&Mp,    g_M);

    // K1: qkv = W_qkv @ x
    dim3 g1(HWN / 128, OC3 / 64, BATCH);
    gemm_kernel<<<g1, 256>>>(qkv_w, 0,
                             x, (size_t)CDIM * HWN,
                             qkv, (size_t)OC3 * HWN, CDIM);

    // K2: depthwise 3x3
    dwconv_kernel<<<(BATCH * OC3 * HWN / 4) / 256, 256>>>(qkv, dw_w, convp);

    // K3: gram reduction
    zero_gram<<<(BATCH * NHEADS * 624 + 255) / 256, 256>>>();
    dim3 g3(64, BATCH * NHEADS);
    gram_kernel<<<g3, 256>>>(convp);

    // K4: softmax + fold proj into per-batch 192x192 matrix
    attn_proj_kernel<<<BATCH, 256>>>(proj_w, temp);

    // K5: out = M_b @ v
    dim3 g5(HWN / 128, CDIM / 64, BATCH);
    gemm_kernel<<<g5, 256>>>(Mp, (size_t)CDIM * CDIM,
                             convp + (size_t)2 * CDIM * HWN, (size_t)OC3 * HWN,
                             out, (size_t)CDIM * HWN, CDIM);
}

// round 4
// speedup vs baseline: 2.0936x; 2.0936x over previous
#include <cuda_runtime.h>
#include <stdint.h>
#include <math.h>

#define BATCH  4
#define CDIM   192
#define NHEADS 8
#define HDIM   24
#define HWN    65536
#define OC3    576
#define KDIM   192
#define NTILES 8
#define KPAD   196
#define NPAD   136

// ---- scratch (device globals) ----
__device__ float g_qkv [(size_t)BATCH * OC3 * HWN];
__device__ float g_conv[(size_t)BATCH * OC3 * HWN];
__device__ float g_gram[BATCH * NHEADS * 624];
__device__ float g_M   [BATCH * CDIM * CDIM];

__device__ __forceinline__ float tf32r(float x) {
    uint32_t o;
    asm("cvt.rna.tf32.f32 %0, %1;" : "=r"(o) : "f"(x));
    return __uint_as_float(o);
}

#define MMA_TF32(cc, aa, b0, b1) \
    asm volatile("mma.sync.aligned.m16n8k8.row.col.f32.tf32.tf32.f32 " \
        "{%0,%1,%2,%3}, {%4,%5,%6,%7}, {%8,%9}, {%0,%1,%2,%3};" \
        : "+f"((cc)[0]), "+f"((cc)[1]), "+f"((cc)[2]), "+f"((cc)[3]) \
        : "r"((aa)[0]), "r"((aa)[1]), "r"((aa)[2]), "r"((aa)[3]), "r"(b0), "r"(b1))

// ============================================================
// TF32 HMMA GEMM: C[b][m][n] = sum_k A[b][m][k] * B[b][k][n]
// CTA: 128m x 128n tile, K=192, loops NTILES n-tiles of 128.
// 256 threads = 8 warps (4m x 2n), warp tile 32m x 64n.
// A resident in smem (tf32), B 64k-chunks double-buffered with
// register prefetch overlapping the MMA mainloop.
// ============================================================
__global__ __launch_bounds__(256) void gemm_tf32(
    const float* __restrict__ A, size_t aStride, int Mreal,
    const float* __restrict__ B, size_t bStride,
    float* __restrict__ C, size_t cStride)
{
    extern __shared__ float smem[];
    float* As  = smem;                    // [128][KPAD]
    float* Bs0 = smem + 128 * KPAD;       // [64][NPAD]
    float* Bs1 = Bs0 + 64 * NPAD;

    int tid  = threadIdx.x;
    int warp = tid >> 5, lane = tid & 31;
    int g = lane >> 2, t = lane & 3;
    int wm0 = (warp >> 1) * 32;
    int wn0 = (warp & 1) * 64;

    int m0    = blockIdx.x * 128;
    int b     = blockIdx.z;
    int nBase = blockIdx.y * (128 * NTILES);
    const float* Ab = A + (size_t)b * aStride;
    const float* Bb = B + (size_t)b * bStride;
    float*       Cb = C + (size_t)b * cStride;

    // ---- load A tile (128 x 192) with round-to-nearest tf32; zero-pad rows ----
    for (int it = tid; it < 128 * 48; it += 256) {
        int row = it / 48, c4 = (it - row * 48) * 4;
        float4 v = make_float4(0.f, 0.f, 0.f, 0.f);
        if (m0 + row < Mreal) v = *(const float4*)&Ab[(size_t)(m0 + row) * KDIM + c4];
        float* d = &As[row * KPAD + c4];
        d[0] = tf32r(v.x); d[1] = tf32r(v.y); d[2] = tf32r(v.z); d[3] = tf32r(v.w);
    }

    int lkr = tid >> 5;            // B loader: k-row base 0..7
    int lc4 = (lane) * 4;          // col within 128
    float4 pf[8];

    float c[2][8][4];
#pragma unroll
    for (int mt = 0; mt < 2; mt++)
#pragma unroll
        for (int nt = 0; nt < 8; nt++)
#pragma unroll
            for (int j = 0; j < 4; j++) c[mt][nt][j] = 0.f;

    const int TOT = NTILES * 3;

    // prologue: load chunk 0
    {
        const float* src = Bb + (size_t)lkr * HWN + nBase + lc4;
#pragma unroll
        for (int j = 0; j < 8; j++) pf[j] = *(const float4*)(src + (size_t)j * 8 * HWN);
#pragma unroll
        for (int j = 0; j < 8; j++) {
            float4 o = {tf32r(pf[j].x), tf32r(pf[j].y), tf32r(pf[j].z), tf32r(pf[j].w)};
            *(float4*)&Bs0[(lkr + j * 8) * NPAD + lc4] = o;
        }
    }
    __syncthreads();

    for (int i = 0; i < TOT; i++) {
        int tile = i / 3;
        int kc   = i - tile * 3;

        // prefetch next chunk into registers (hidden under MMAs)
        if (i + 1 < TOT) {
            int ntile = (i + 1) / 3;
            int nkc   = (i + 1) - ntile * 3;
            const float* src = Bb + (size_t)(nkc * 64 + lkr) * HWN
                                  + nBase + ntile * 128 + lc4;
#pragma unroll
            for (int j = 0; j < 8; j++) pf[j] = *(const float4*)(src + (size_t)j * 8 * HWN);
        }

        // ---- MMA mainloop on current chunk ----
        const float* buf = (i & 1) ? Bs1 : Bs0;
#pragma unroll
        for (int k8 = 0; k8 < 8; k8++) {
            int kA = kc * 64 + k8 * 8;
            uint32_t a[2][4];
#pragma unroll
            for (int mt = 0; mt < 2; mt++) {
                const float* ar = &As[(wm0 + mt * 16 + g) * KPAD + kA + t];
                a[mt][0] = __float_as_uint(ar[0]);
                a[mt][1] = __float_as_uint(ar[8 * KPAD]);
                a[mt][2] = __float_as_uint(ar[4]);
                a[mt][3] = __float_as_uint(ar[8 * KPAD + 4]);
            }
#pragma unroll
            for (int nt = 0; nt < 8; nt++) {
                const float* br = &buf[(k8 * 8 + t) * NPAD + wn0 + nt * 8 + g];
                uint32_t b0 = __float_as_uint(br[0]);
                uint32_t b1 = __float_as_uint(br[4 * NPAD]);
                MMA_TF32(c[0][nt], a[0], b0, b1);
                MMA_TF32(c[1][nt], a[1], b0, b1);
            }
        }

        // ---- epilogue after last chunk of a tile ----
        if (kc == 2) {
            int n0 = nBase + tile * 128;
#pragma unroll
            for (int mt = 0; mt < 2; mt++) {
                int row0 = m0 + wm0 + mt * 16 + g;
#pragma unroll
                for (int nt = 0; nt < 8; nt++) {
                    int col = n0 + wn0 + nt * 8 + 2 * t;
                    if (row0 < Mreal) {
                        float2 v = {c[mt][nt][0], c[mt][nt][1]};
                        *(float2*)&Cb[(size_t)row0 * HWN + col] = v;
                    }
                    if (row0 + 8 < Mreal) {
                        float2 v = {c[mt][nt][2], c[mt][nt][3]};
                        *(float2*)&Cb[(size_t)(row0 + 8) * HWN + col] = v;
                    }
                    c[mt][nt][0] = 0.f; c[mt][nt][1] = 0.f;
                    c[mt][nt][2] = 0.f; c[mt][nt][3] = 0.f;
                }
            }
        }

        // ---- store prefetched chunk, flip buffer ----
        if (i + 1 < TOT) {
            float* nbuf = (i & 1) ? Bs0 : Bs1;
#pragma unroll
            for (int j = 0; j < 8; j++) {
                float4 o = {tf32r(pf[j].x), tf32r(pf[j].y), tf32r(pf[j].z), tf32r(pf[j].w)};
                *(float4*)&nbuf[(lkr + j * 8) * NPAD + lc4] = o;
            }
            __syncthreads();
        }
    }
}

// ============================================================
// depthwise 3x3, pad=1
// ============================================================
__global__ __launch_bounds__(256) void dwconv_kernel(
    const float* __restrict__ in, const float* __restrict__ wAll,
    float* __restrict__ out)
{
    int idx = blockIdx.x * 256 + threadIdx.x;
    int p4 = idx & 16383;
    int bc = idx >> 14;
    int ch = bc % OC3;
    int y  = p4 >> 6;
    int x0 = (p4 & 63) << 2;
    const float* base = in + (size_t)bc * HWN;

    float w[9];
#pragma unroll
    for (int i = 0; i < 9; i++) w[i] = __ldg(&wAll[ch * 9 + i]);

    float s0 = 0.f, s1 = 0.f, s2 = 0.f, s3 = 0.f;
#pragma unroll
    for (int ky = 0; ky < 3; ky++) {
        int yy = y + ky - 1;
        if ((unsigned)yy >= 256u) continue;
        const float* row = base + yy * 256;
        float4 v    = *(const float4*)&row[x0];
        float left  = (x0 > 0)   ? row[x0 - 1] : 0.f;
        float right = (x0 < 252) ? row[x0 + 4] : 0.f;
        float w0 = w[ky * 3], w1 = w[ky * 3 + 1], w2 = w[ky * 3 + 2];
        s0 += left * w0 + v.x  * w1 + v.y  * w2;
        s1 += v.x  * w0 + v.y  * w1 + v.z  * w2;
        s2 += v.y  * w0 + v.z  * w1 + v.w  * w2;
        s3 += v.z  * w0 + v.w  * w1 + right * w2;
    }
    float4 o = {s0, s1, s2, s3};
    *(float4*)&out[(size_t)idx * 4] = o;
}

__global__ void zero_gram() {
    int i = blockIdx.x * blockDim.x + threadIdx.x;
    if (i < BATCH * NHEADS * 624) g_gram[i] = 0.f;
}

// ============================================================
// gram: register-tiled 3x3 per thread, atomic partials
// ============================================================
__global__ __launch_bounds__(256) void gram_kernel(const float* __restrict__ conv)
{
    __shared__ float qs[24][68];
    __shared__ float ks[24][68];
    int bh = blockIdx.y;
    int b = bh >> 3, hh = bh & 7;
    const float* qb = conv + ((size_t)b * OC3 + hh * HDIM) * HWN;
    const float* kb = conv + ((size_t)b * OC3 + CDIM + hh * HDIM) * HWN;

    int t = threadIdx.x;
    int slice = t >> 6;
    int p = t & 63;
    int ty = p >> 3, tx = p & 7;
    int d0 = ty * 3, e0 = tx * 3;
    int ns = slice * 16;

    float a00=0,a01=0,a02=0,a10=0,a11=0,a12=0,a20=0,a21=0,a22=0;
    float nacc = 0.f;

    int nStart = blockIdx.x * 1024;
#pragma unroll 1
    for (int n0 = nStart; n0 < nStart + 1024; n0 += 64) {
        __syncthreads();
        for (int i = t; i < 24 * 16; i += 256) {
            int r = i >> 4, c4 = (i & 15) << 2;
            *(float4*)&qs[r][c4] = *(const float4*)&qb[(size_t)r * HWN + n0 + c4];
            *(float4*)&ks[r][c4] = *(const float4*)&kb[(size_t)r * HWN + n0 + c4];
        }
        __syncthreads();
#pragma unroll
        for (int n = 0; n < 16; n++) {
            int nn = ns + n;
            float q0 = qs[d0][nn], q1 = qs[d0+1][nn], q2 = qs[d0+2][nn];
            float k0 = ks[e0][nn], k1 = ks[e0+1][nn], k2 = ks[e0+2][nn];
            a00 += q0*k0; a01 += q0*k1; a02 += q0*k2;
            a10 += q1*k0; a11 += q1*k1; a12 += q1*k2;
            a20 += q2*k0; a21 += q2*k1; a22 += q2*k2;
        }
        if (p < 48) {
            const float* row = (p < 24) ? qs[p] : ks[p - 24];
#pragma unroll
            for (int n = 0; n < 16; n++) { float v = row[ns + n]; nacc += v * v; }
        }
    }
    float* gb = &g_gram[bh * 624];
    atomicAdd(&gb[(d0+0)*24 + e0+0], a00); atomicAdd(&gb[(d0+0)*24 + e0+1], a01); atomicAdd(&gb[(d0+0)*24 + e0+2], a02);
    atomicAdd(&gb[(d0+1)*24 + e0+0], a10); atomicAdd(&gb[(d0+1)*24 + e0+1], a11); atomicAdd(&gb[(d0+1)*24 + e0+2], a12);
    atomicAdd(&gb[(d0+2)*24 + e0+0], a20); atomicAdd(&gb[(d0+2)*24 + e0+1], a21); atomicAdd(&gb[(d0+2)*24 + e0+2], a22);
    if (p < 48) atomicAdd(&gb[576 + p], nacc);
}

// ============================================================
// softmax + fold proj -> per-batch M (fp32)
// ============================================================
__global__ __launch_bounds__(256) void attn_proj_kernel(
    const float* __restrict__ projw, const float* __restrict__ temp)
{
    __shared__ float attn_s[NHEADS * HDIM * HDIM];
    int b = blockIdx.x;
    int t = threadIdx.x;
    if (t < CDIM) {
        int hh = t / HDIM, d = t % HDIM;
        const float* G = &g_gram[(b * NHEADS + hh) * 624];
        float nq = fmaxf(sqrtf(G[576 + d]), 1e-12f);
        float tm = temp[hh];
        float row[HDIM];
        float mx = -1e30f;
#pragma unroll
        for (int e = 0; e < HDIM; e++) {
            float nk = fmaxf(sqrtf(G[600 + e]), 1e-12f);
            float a = G[d * 24 + e] / (nq * nk) * tm;
            row[e] = a; mx = fmaxf(mx, a);
        }
        float s = 0.f;
#pragma unroll
        for (int e = 0; e < HDIM; e++) { row[e] = expf(row[e] - mx); s += row[e]; }
        float inv = 1.f / s;
#pragma unroll
        for (int e = 0; e < HDIM; e++) attn_s[hh * 576 + d * 24 + e] = row[e] * inv;
    }
    __syncthreads();
    if (t < CDIM) {
        int o = t;
        const float* pr = &projw[o * CDIM];
        for (int hh = 0; hh < NHEADS; hh++) {
#pragma unroll
            for (int e = 0; e < HDIM; e++) {
                float acc = 0.f;
#pragma unroll
                for (int d = 0; d < HDIM; d++)
                    acc += pr[hh * 24 + d] * attn_s[hh * 576 + d * 24 + e];
                g_M[((size_t)b * CDIM + o) * CDIM + hh * 24 + e] = acc;
            }
        }
    }
}

// ============================================================
extern "C" void kernel_launch(void* const* d_in, const int* in_sizes, int n_in,
                              void* d_out, int out_size)
{
    const float* x      = (const float*)d_in[0];
    const float* qkv_w  = (const float*)d_in[1];
    const float* dw_w   = (const float*)d_in[2];
    const float* proj_w = (const float*)d_in[3];
    const float* temp   = (const float*)d_in[4];
    float* out = (float*)d_out;

    float *qkv, *convp, *Mp;
    cudaGetSymbolAddress((void**)&qkv,   g_qkv);
    cudaGetSymbolAddress((void**)&convp, g_conv);
    cudaGetSymbolAddress((void**)&Mp,    g_M);

    const int SMEMSZ = (128 * KPAD + 2 * 64 * NPAD) * 4;   // 169,984 B
    cudaFuncSetAttribute(gemm_tf32, cudaFuncAttributeMaxDynamicSharedMemorySize, SMEMSZ);

    zero_gram<<<(BATCH * NHEADS * 624 + 255) / 256, 256>>>();

    // K1: qkv = W_qkv @ x   (tf32 tensor cores)
    dim3 g1(5, HWN / (128 * NTILES), BATCH);
    gemm_tf32<<<g1, 256, SMEMSZ>>>(qkv_w, 0, OC3,
                                   x, (size_t)CDIM * HWN,
                                   qkv, (size_t)OC3 * HWN);

    // K2: depthwise 3x3
    dwconv_kernel<<<(BATCH * OC3 * HWN / 4) / 256, 256>>>(qkv, dw_w, convp);

    // K3: gram reduction
    dim3 g3(64, BATCH * NHEADS);
    gram_kernel<<<g3, 256>>>(convp);

    // K4: softmax + fold proj into per-batch 192x192 matrix
    attn_proj_kernel<<<BATCH, 256>>>(proj_w, temp);

    // K5: out = M_b @ v   (tf32 tensor cores)
    dim3 g5(2, HWN / (128 * NTILES), BATCH);
    gemm_tf32<<<g5, 256, SMEMSZ>>>(Mp, (size_t)CDIM * CDIM, CDIM,
                                   convp + (size_t)2 * CDIM * HWN, (size_t)OC3 * HWN,
                                   out, (size_t)CDIM * HWN);
}

// round 6
// speedup vs baseline: 2.2228x; 1.0617x over previous
#include <cuda_runtime.h>
#include <cuda_fp16.h>
#include <stdint.h>
#include <math.h>

#define BATCH  4
#define CDIM   192
#define NHEADS 8
#define HDIM   24
#define HWN    65536
#define OC3    576
#define KDIM   192
#define NTILES 8
#define KPADH  200   // A row pad (halves)
#define NPADH  136   // B row pad (halves)

// ---- scratch (device globals) ----
__device__ float  g_qkv [(size_t)BATCH * OC3 * HWN];
__device__ __half g_vh  [(size_t)BATCH * CDIM * HWN];
__device__ float  g_gram[BATCH * NHEADS * 624];
__device__ float  g_M   [BATCH * CDIM * CDIM];

__device__ __forceinline__ uint32_t smem_u32(const void* p) {
    uint32_t a;
    asm("{ .reg .u64 t; cvta.to.shared.u64 t, %1; cvt.u32.u64 %0, t; }" : "=r"(a) : "l"(p));
    return a;
}
__device__ __forceinline__ uint32_t h2u(__half2 h) { return *(uint32_t*)&h; }

#define LDSM_X4(r, addr) \
    asm volatile("ldmatrix.sync.aligned.m8n8.x4.shared.b16 {%0,%1,%2,%3}, [%4];" \
        : "=r"((r)[0]), "=r"((r)[1]), "=r"((r)[2]), "=r"((r)[3]) : "r"(addr))
#define LDSM_X4_T(r, addr) \
    asm volatile("ldmatrix.sync.aligned.m8n8.x4.trans.shared.b16 {%0,%1,%2,%3}, [%4];" \
        : "=r"((r)[0]), "=r"((r)[1]), "=r"((r)[2]), "=r"((r)[3]) : "r"(addr))
#define MMA_F16(cc, aa, b0, b1) \
    asm volatile("mma.sync.aligned.m16n8k16.row.col.f32.f16.f16.f32 " \
        "{%0,%1,%2,%3}, {%4,%5,%6,%7}, {%8,%9}, {%0,%1,%2,%3};" \
        : "+f"((cc)[0]), "+f"((cc)[1]), "+f"((cc)[2]), "+f"((cc)[3]) \
        : "r"((aa)[0]), "r"((aa)[1]), "r"((aa)[2]), "r"((aa)[3]), "r"(b0), "r"(b1))

// ============================================================
// fp16 HMMA GEMM: C[b][m][n] = sum_k A[b][m][k] * B[b][k][n]
// 128m x 128n CTA tile, K=192 in 3 chunks of 64, double-buffered B,
// register prefetch. 8 warps (4m x 2n). BH: B already fp16 in gmem.
// ============================================================
template<bool BH>
__global__ __launch_bounds__(256) void gemm_f16(
    const float* __restrict__ A, size_t aStride, int Mreal,
    const void* __restrict__ Bv, size_t bStride,
    float* __restrict__ C, size_t cStride)
{
    extern __shared__ __half hsm[];
    __half* As  = hsm;                       // [128][KPADH]
    __half* Bs0 = As + 128 * KPADH;          // [64][NPADH]
    __half* Bs1 = Bs0 + 64 * NPADH;

    const float*  Bf = (const float*)Bv;
    const __half* Bh = (const __half*)Bv;

    int tid  = threadIdx.x;
    int warp = tid >> 5, lane = tid & 31;
    int g = lane >> 2, t = lane & 3;
    int wm0 = (warp >> 1) * 32;
    int wn0 = (warp & 1) * 64;

    int m0    = blockIdx.x * 128;
    int b     = blockIdx.z;
    int nBase = blockIdx.y * (128 * NTILES);
    const float* Ab = A + (size_t)b * aStride;
    size_t bOff = (size_t)b * bStride;
    float* Cb = C + (size_t)b * cStride;

    // ---- load A tile -> fp16 smem, zero-pad rows >= Mreal ----
    for (int it = tid; it < 128 * 48; it += 256) {
        int row = it / 48, c4 = (it - row * 48) * 4;
        float4 v = make_float4(0.f, 0.f, 0.f, 0.f);
        if (m0 + row < Mreal) v = *(const float4*)&Ab[(size_t)(m0 + row) * KDIM + c4];
        uint2 u;
        u.x = h2u(__float22half2_rn(make_float2(v.x, v.y)));
        u.y = h2u(__float22half2_rn(make_float2(v.z, v.w)));
        *(uint2*)(As + row * KPADH + c4) = u;
    }

    int kr  = tid >> 5;            // k-row base (0..7), rows kr+8j
    int lc4 = lane * 4;            // col group
    float4 pf[8];
    uint2  pf2[8];

    float c[2][8][4];
#pragma unroll
    for (int mt = 0; mt < 2; mt++)
#pragma unroll
        for (int nt = 0; nt < 8; nt++)
#pragma unroll
            for (int j = 0; j < 4; j++) c[mt][nt][j] = 0.f;

    const int TOT = NTILES * 3;
    uint32_t sA  = smem_u32(As);
    uint32_t sB0 = smem_u32(Bs0);
    uint32_t sB1 = smem_u32(Bs1);

    // prologue: chunk 0
    {
        if (BH) {
#pragma unroll
            for (int j = 0; j < 8; j++)
                pf2[j] = *(const uint2*)&Bh[bOff + (size_t)(kr + 8 * j) * HWN + nBase + lc4];
        } else {
#pragma unroll
            for (int j = 0; j < 8; j++)
                pf[j] = *(const float4*)&Bf[bOff + (size_t)(kr + 8 * j) * HWN + nBase + lc4];
        }
#pragma unroll
        for (int j = 0; j < 8; j++) {
            uint2 u;
            if (BH) u = pf2[j];
            else {
                u.x = h2u(__float22half2_rn(make_float2(pf[j].x, pf[j].y)));
                u.y = h2u(__float22half2_rn(make_float2(pf[j].z, pf[j].w)));
            }
            *(uint2*)(Bs0 + (kr + 8 * j) * NPADH + lc4) = u;
        }
    }
    __syncthreads();

    for (int i = 0; i < TOT; i++) {
        int tile = i / 3;
        int kc   = i - tile * 3;

        // prefetch next chunk
        if (i + 1 < TOT) {
            int ntile = (i + 1) / 3;
            int nkc   = (i + 1) - ntile * 3;
            size_t src = bOff + (size_t)(nkc * 64 + kr) * HWN + nBase + ntile * 128 + lc4;
            if (BH) {
#pragma unroll
                for (int j = 0; j < 8; j++) pf2[j] = *(const uint2*)&Bh[src + (size_t)j * 8 * HWN];
            } else {
#pragma unroll
                for (int j = 0; j < 8; j++) pf[j] = *(const float4*)&Bf[src + (size_t)j * 8 * HWN];
            }
        }

        // ---- MMA on current chunk (4 k16-steps) ----
        uint32_t sB = (i & 1) ? sB1 : sB0;
#pragma unroll
        for (int ks = 0; ks < 4; ks++) {
            uint32_t a[2][4];
            int kA = kc * 64 + ks * 16 + ((lane >> 4) << 3);
#pragma unroll
            for (int mt = 0; mt < 2; mt++) {
                int row = wm0 + mt * 16 + (lane & 15);
                LDSM_X4(a[mt], sA + (uint32_t)(row * KPADH + kA) * 2);
            }
#pragma unroll
            for (int pr = 0; pr < 4; pr++) {
                uint32_t bq[4];
                int brow = ks * 16 + (lane & 15);
                int bcol = wn0 + pr * 16 + ((lane >> 4) << 3);
                LDSM_X4_T(bq, sB + (uint32_t)(brow * NPADH + bcol) * 2);
                MMA_F16(c[0][2 * pr],     a[0], bq[0], bq[1]);
                MMA_F16(c[1][2 * pr],     a[1], bq[0], bq[1]);
                MMA_F16(c[0][2 * pr + 1], a[0], bq[2], bq[3]);
                MMA_F16(c[1][2 * pr + 1], a[1], bq[2], bq[3]);
            }
        }

        // ---- epilogue at tile end ----
        if (kc == 2) {
            int n0 = nBase + tile * 128;
#pragma unroll
            for (int mt = 0; mt < 2; mt++) {
                int row0 = m0 + wm0 + mt * 16 + g;
#pragma unroll
                for (int nt = 0; nt < 8; nt++) {
                    int col = n0 + wn0 + nt * 8 + 2 * t;
                    if (row0 < Mreal) {
                        float2 v = {c[mt][nt][0], c[mt][nt][1]};
                        *(float2*)&Cb[(size_t)row0 * HWN + col] = v;
                    }
                    if (row0 + 8 < Mreal) {
                        float2 v = {c[mt][nt][2], c[mt][nt][3]};
                        *(float2*)&Cb[(size_t)(row0 + 8) * HWN + col] = v;
                    }
                    c[mt][nt][0] = 0.f; c[mt][nt][1] = 0.f;
                    c[mt][nt][2] = 0.f; c[mt][nt][3] = 0.f;
                }
            }
        }

        // ---- store prefetched chunk, flip ----
        if (i + 1 < TOT) {
            __half* nbuf = (i & 1) ? Bs0 : Bs1;
#pragma unroll
            for (int j = 0; j < 8; j++) {
                uint2 u;
                if (BH) u = pf2[j];
                else {
                    u.x = h2u(__float22half2_rn(make_float2(pf[j].x, pf[j].y)));
                    u.y = h2u(__float22half2_rn(make_float2(pf[j].z, pf[j].w)));
                }
                *(uint2*)(nbuf + (kr + 8 * j) * NPADH + lc4) = u;
            }
            __syncthreads();
        }
    }
}

// ============================================================
// depthwise 3x3 for v channels only, fp16 output
// ============================================================
__global__ __launch_bounds__(256) void dwconv_v(
    const float* __restrict__ qkv, const float* __restrict__ wAll,
    __half* __restrict__ out)
{
    int idx = blockIdx.x * 256 + threadIdx.x;    // BATCH*CDIM*HWN/4
    int p4 = idx & 16383;
    int bc = idx >> 14;                          // b*192 + ch
    int b  = bc / CDIM;
    int ch = bc - b * CDIM;
    int gch = 2 * CDIM + ch;
    int y  = p4 >> 6;
    int x0 = (p4 & 63) << 2;
    const float* base = qkv + ((size_t)b * OC3 + gch) * HWN;

    float w[9];
#pragma unroll
    for (int i = 0; i < 9; i++) w[i] = __ldg(&wAll[gch * 9 + i]);

    float s0 = 0.f, s1 = 0.f, s2 = 0.f, s3 = 0.f;
#pragma unroll
    for (int ky = 0; ky < 3; ky++) {
        int yy = y + ky - 1;
        if ((unsigned)yy >= 256u) continue;
        const float* row = base + yy * 256;
        float4 v    = *(const float4*)&row[x0];
        float left  = (x0 > 0)   ? row[x0 - 1] : 0.f;
        float right = (x0 < 252) ? row[x0 + 4] : 0.f;
        float w0 = w[ky * 3], w1 = w[ky * 3 + 1], w2 = w[ky * 3 + 2];
        s0 += left * w0 + v.x  * w1 + v.y  * w2;
        s1 += v.x  * w0 + v.y  * w1 + v.z  * w2;
        s2 += v.y  * w0 + v.z  * w1 + v.w  * w2;
        s3 += v.z  * w0 + v.w  * w1 + right * w2;
    }
    uint2 u;
    u.x = h2u(__float22half2_rn(make_float2(s0, s1)));
    u.y = h2u(__float22half2_rn(make_float2(s2, s3)));
    *(uint2*)&out[(size_t)idx * 4] = u;
}

__global__ void zero_gram() {
    int i = blockIdx.x * blockDim.x + threadIdx.x;
    if (i < BATCH * NHEADS * 624) g_gram[i] = 0.f;
}

// ============================================================
// Fused dwconv(q,k) + gram. CTA = (b,h) x 128-px column block x 32-row strip.
// Rolling 3-row qkv window in smem; conv row in smem; 6x6 register gram tile.
// ============================================================
#define WROW 132          // window row pad (floats)
#define CROW 129          // conv row pad (floats)
__global__ __launch_bounds__(256) void dwgram_kernel(
    const float* __restrict__ qkv, const float* __restrict__ dw_w)
{
    extern __shared__ float dsm[];
    float* win = dsm;                       // [48][3][WROW]
    float* cv  = dsm + 48 * 3 * WROW;       // [48][CROW]
    float* ws  = cv + 48 * CROW;            // [48][9]

    int bh = blockIdx.y;
    int b = bh >> 3, hh = bh & 7;
    int xb = blockIdx.x & 1;
    int strip = blockIdx.x >> 1;
    int y0 = strip * 32;
    int gx0 = xb * 128;
    int tid = threadIdx.x;

    for (int i = tid; i < 48 * 9; i += 256) {
        int c = i / 9, tt = i - c * 9;
        int gch = (c < 24) ? (hh * HDIM + c) : (CDIM + hh * HDIM + (c - 24));
        ws[i] = dw_w[gch * 9 + tt];
    }

    // row loader (no internal sync)
#define LOAD_ROW(r) do { \
    int slot = ((r) + 3) % 3; \
    for (int i = tid; i < 48 * 130; i += 256) { \
        int c = i / 130, j = i - c * 130; \
        int gxx = gx0 - 1 + j; \
        float v = 0.f; \
        if ((unsigned)(r) < 256u && (unsigned)gxx < 256u) { \
            int gch = (c < 24) ? (hh * HDIM + c) : (CDIM + hh * HDIM + (c - 24)); \
            v = qkv[((size_t)b * OC3 + gch) * HWN + (r) * 256 + gxx]; \
        } \
        win[(c * 3 + slot) * WROW + j] = v; \
    } } while (0)

    LOAD_ROW(y0 - 1);
    LOAD_ROW(y0);

    int p = tid & 15, slice = tid >> 4;
    int ty = p >> 2, tx = p & 3;
    int d0 = ty * 6, e0 = tx * 6;
    int xs = slice * 8;

    float acc[6][6];
#pragma unroll
    for (int i = 0; i < 6; i++)
#pragma unroll
        for (int j = 0; j < 6; j++) acc[i][j] = 0.f;
    float nacc[3] = {0.f, 0.f, 0.f};

    for (int y = y0; y < y0 + 32; y++) {
        LOAD_ROW(y + 1);
        __syncthreads();
        int s0 = (y + 2) % 3, s1 = (y + 3) % 3, s2 = (y + 4) % 3;
        // conv: 4 px per thread
        for (int i = tid; i < 48 * 32; i += 256) {
            int c = i >> 5, x4 = (i & 31) << 2;
            const float* w9 = &ws[c * 9];
            const float* wr = &win[c * 3 * WROW];
            float r0[6], r1[6], r2[6];
#pragma unroll
            for (int j = 0; j < 6; j++) {
                r0[j] = wr[s0 * WROW + x4 + j];
                r1[j] = wr[s1 * WROW + x4 + j];
                r2[j] = wr[s2 * WROW + x4 + j];
            }
#pragma unroll
            for (int o = 0; o < 4; o++) {
                cv[c * CROW + x4 + o] =
                    r0[o] * w9[0] + r0[o+1] * w9[1] + r0[o+2] * w9[2]
                  + r1[o] * w9[3] + r1[o+1] * w9[4] + r1[o+2] * w9[5]
                  + r2[o] * w9[6] + r2[o+1] * w9[7] + r2[o+2] * w9[8];
            }
        }
        __syncthreads();
        // gram 6x6 tile over 8-px slice
#pragma unroll
        for (int n = 0; n < 8; n++) {
            int nn = xs + n;
            float q[6], k[6];
#pragma unroll
            for (int r = 0; r < 6; r++) q[r] = cv[(d0 + r) * CROW + nn];
#pragma unroll
            for (int r = 0; r < 6; r++) k[r] = cv[(24 + e0 + r) * CROW + nn];
#pragma unroll
            for (int i = 0; i < 6; i++)
#pragma unroll
                for (int j = 0; j < 6; j++) acc[i][j] += q[i] * k[j];
#pragma unroll
            for (int r = 0; r < 3; r++) {
                float v = cv[(3 * p + r) * CROW + nn];
                nacc[r] += v * v;
            }
        }
    }

    float* gb = &g_gram[bh * 624];
#pragma unroll
    for (int i = 0; i < 6; i++)
#pragma unroll
        for (int j = 0; j < 6; j++)
            atomicAdd(&gb[(d0 + i) * 24 + e0 + j], acc[i][j]);
#pragma unroll
    for (int r = 0; r < 3; r++) atomicAdd(&gb[576 + 3 * p + r], nacc[r]);
#undef LOAD_ROW
}

// ============================================================
// softmax + fold proj -> per-batch M (fp32)
// ============================================================
__global__ __launch_bounds__(256) void attn_proj_kernel(
    const float* __restrict__ projw, const float* __restrict__ temp)
{
    __shared__ float attn_s[NHEADS * HDIM * HDIM];
    int b = blockIdx.x;
    int t = threadIdx.x;
    if (t < CDIM) {
        int hh = t / HDIM, d = t % HDIM;
        const float* G = &g_gram[(b * NHEADS + hh) * 624];
        float nq = fmaxf(sqrtf(G[576 + d]), 1e-12f);
        float tm = temp[hh];
        float row[HDIM];
        float mx = -1e30f;
#pragma unroll
        for (int e = 0; e < HDIM; e++) {
            float nk = fmaxf(sqrtf(G[600 + e]), 1e-12f);
            float a = G[d * 24 + e] / (nq * nk) * tm;
            row[e] = a; mx = fmaxf(mx, a);
        }
        float s = 0.f;
#pragma unroll
        for (int e = 0; e < HDIM; e++) { row[e] = expf(row[e] - mx); s += row[e]; }
        float inv = 1.f / s;
#pragma unroll
        for (int e = 0; e < HDIM; e++) attn_s[hh * 576 + d * 24 + e] = row[e] * inv;
    }
    __syncthreads();
    if (t < CDIM) {
        int o = t;
        const float* pr = &projw[o * CDIM];
        for (int hh = 0; hh < NHEADS; hh++) {
#pragma unroll
            for (int e = 0; e < HDIM; e++) {
                float acc = 0.f;
#pragma unroll
                for (int d = 0; d < HDIM; d++)
                    acc += pr[hh * 24 + d] * attn_s[hh * 576 + d * 24 + e];
                g_M[((size_t)b * CDIM + o) * CDIM + hh * 24 + e] = acc;
            }
        }
    }
}

// ============================================================
extern "C" void kernel_launch(void* const* d_in, const int* in_sizes, int n_in,
                              void* d_out, int out_size)
{
    const float* x      = (const float*)d_in[0];
    const float* qkv_w  = (const float*)d_in[1];
    const float* dw_w   = (const float*)d_in[2];
    const float* proj_w = (const float*)d_in[3];
    const float* temp   = (const float*)d_in[4];
    float* out = (float*)d_out;

    float *qkv, *Mp;
    __half* vh;
    cudaGetSymbolAddress((void**)&qkv, g_qkv);
    cudaGetSymbolAddress((void**)&vh,  g_vh);
    cudaGetSymbolAddress((void**)&Mp,  g_M);

    const int GEMM_SMEM = (128 * KPADH + 2 * 64 * NPADH) * 2;       // 86,016 B
    const int DG_SMEM   = (48 * 3 * WROW + 48 * CROW + 48 * 9) * 4; // 102,528 B
    cudaFuncSetAttribute(gemm_f16<false>, cudaFuncAttributeMaxDynamicSharedMemorySize, GEMM_SMEM);
    cudaFuncSetAttribute(gemm_f16<true>,  cudaFuncAttributeMaxDynamicSharedMemorySize, GEMM_SMEM);
    cudaFuncSetAttribute(dwgram_kernel,   cudaFuncAttributeMaxDynamicSharedMemorySize, DG_SMEM);

    zero_gram<<<(BATCH * NHEADS * 624 + 255) / 256, 256>>>();

    // K1: qkv = W_qkv @ x   (fp16 tensor cores, fp32 B in gmem)
    dim3 g1(5, HWN / (128 * NTILES), BATCH);
    gemm_f16<false><<<g1, 256, GEMM_SMEM>>>(qkv_w, 0, OC3,
                                            x, (size_t)CDIM * HWN,
                                            qkv, (size_t)OC3 * HWN);

    // K2: depthwise 3x3 on v only -> fp16
    dwconv_v<<<(BATCH * CDIM * HWN / 4) / 256, 256>>>(qkv, dw_w, vh);

    // K3: fused dwconv(q,k) + gram
    dim3 g3(16, BATCH * NHEADS);
    dwgram_kernel<<<g3, 256, DG_SMEM>>>(qkv, dw_w);

    // K4: softmax + fold proj
    attn_proj_kernel<<<BATCH, 256>>>(proj_w, temp);

    // K5: out = M_b @ v   (fp16 tensor cores, fp16 B in gmem)
    dim3 g5(2, HWN / (128 * NTILES), BATCH);
    gemm_f16<true><<<g5, 256, GEMM_SMEM>>>(Mp, (size_t)CDIM * CDIM, CDIM,
                                           vh, (size_t)CDIM * HWN,
                                           out, (size_t)CDIM * HWN);
}

// round 7
// speedup vs baseline: 3.0804x; 1.3858x over previous
#include <cuda_runtime.h>
#include <cuda_fp16.h>
#include <stdint.h>
#include <math.h>

#define BATCH  4
#define CDIM   192
#define NHEADS 8
#define HDIM   24
#define HWN    65536
#define OC3    576
#define KDIM   192
#define NTILES 8
#define KPADH  200   // A row pad (halves)
#define NPADH  136   // B row pad (halves)

// ---- scratch (device globals) ----
__device__ __half g_qkvh[(size_t)BATCH * OC3 * HWN];  // 1x1-conv out, fp16
__device__ __half g_ch  [(size_t)BATCH * OC3 * HWN];  // dwconv out, fp16
__device__ float  g_g48 [BATCH * NHEADS * 48 * 48];   // [q;k] full gram
__device__ float  g_M   [BATCH * CDIM * CDIM];

__device__ __forceinline__ uint32_t smem_u32(const void* p) {
    uint32_t a;
    asm("{ .reg .u64 t; cvta.to.shared.u64 t, %1; cvt.u32.u64 %0, t; }" : "=r"(a) : "l"(p));
    return a;
}
__device__ __forceinline__ uint32_t h2u(__half2 h) { return *(uint32_t*)&h; }

#define LDSM_X4(r, addr) \
    asm volatile("ldmatrix.sync.aligned.m8n8.x4.shared.b16 {%0,%1,%2,%3}, [%4];" \
        : "=r"((r)[0]), "=r"((r)[1]), "=r"((r)[2]), "=r"((r)[3]) : "r"(addr))
#define LDSM_X4_T(r, addr) \
    asm volatile("ldmatrix.sync.aligned.m8n8.x4.trans.shared.b16 {%0,%1,%2,%3}, [%4];" \
        : "=r"((r)[0]), "=r"((r)[1]), "=r"((r)[2]), "=r"((r)[3]) : "r"(addr))
#define MMA_F16(cc, aa, b0, b1) \
    asm volatile("mma.sync.aligned.m16n8k16.row.col.f32.f16.f16.f32 " \
        "{%0,%1,%2,%3}, {%4,%5,%6,%7}, {%8,%9}, {%0,%1,%2,%3};" \
        : "+f"((cc)[0]), "+f"((cc)[1]), "+f"((cc)[2]), "+f"((cc)[3]) \
        : "r"((aa)[0]), "r"((aa)[1]), "r"((aa)[2]), "r"((aa)[3]), "r"(b0), "r"(b1))

// ============================================================
// fp16 HMMA GEMM: C[b][m][n] = sum_k A[b][m][k] * B[b][k][n]
// 128m x 128n CTA tile, K=192 (3 chunks of 64), double-buffered B,
// register prefetch. BH: B fp16 in gmem. OH: C stored fp16.
// ============================================================
template<bool BH, bool OH>
__global__ __launch_bounds__(256) void gemm_f16(
    const float* __restrict__ A, size_t aStride, int Mreal,
    const void* __restrict__ Bv, size_t bStride,
    void* __restrict__ C, size_t cStride)
{
    extern __shared__ __half hsm[];
    __half* As  = hsm;                       // [128][KPADH]
    __half* Bs0 = As + 128 * KPADH;          // [64][NPADH]
    __half* Bs1 = Bs0 + 64 * NPADH;

    const float*  Bf = (const float*)Bv;
    const __half* Bh = (const __half*)Bv;
    float*  Cf = (float*)C;
    __half* Ch = (__half*)C;

    int tid  = threadIdx.x;
    int warp = tid >> 5, lane = tid & 31;
    int g = lane >> 2, t = lane & 3;
    int wm0 = (warp >> 1) * 32;
    int wn0 = (warp & 1) * 64;

    int m0    = blockIdx.x * 128;
    int b     = blockIdx.z;
    int nBase = blockIdx.y * (128 * NTILES);
    const float* Ab = A + (size_t)b * aStride;
    size_t bOff = (size_t)b * bStride;
    size_t cOff = (size_t)b * cStride;

    for (int it = tid; it < 128 * 48; it += 256) {
        int row = it / 48, c4 = (it - row * 48) * 4;
        float4 v = make_float4(0.f, 0.f, 0.f, 0.f);
        if (m0 + row < Mreal) v = *(const float4*)&Ab[(size_t)(m0 + row) * KDIM + c4];
        uint2 u;
        u.x = h2u(__float22half2_rn(make_float2(v.x, v.y)));
        u.y = h2u(__float22half2_rn(make_float2(v.z, v.w)));
        *(uint2*)(As + row * KPADH + c4) = u;
    }

    int kr  = tid >> 5;
    int lc4 = lane * 4;
    float4 pf[8];
    uint2  pf2[8];

    float c[2][8][4];
#pragma unroll
    for (int mt = 0; mt < 2; mt++)
#pragma unroll
        for (int nt = 0; nt < 8; nt++)
#pragma unroll
            for (int j = 0; j < 4; j++) c[mt][nt][j] = 0.f;

    const int TOT = NTILES * 3;
    uint32_t sA  = smem_u32(As);
    uint32_t sB0 = smem_u32(Bs0);
    uint32_t sB1 = smem_u32(Bs1);

    {
        if (BH) {
#pragma unroll
            for (int j = 0; j < 8; j++)
                pf2[j] = *(const uint2*)&Bh[bOff + (size_t)(kr + 8 * j) * HWN + nBase + lc4];
        } else {
#pragma unroll
            for (int j = 0; j < 8; j++)
                pf[j] = *(const float4*)&Bf[bOff + (size_t)(kr + 8 * j) * HWN + nBase + lc4];
        }
#pragma unroll
        for (int j = 0; j < 8; j++) {
            uint2 u;
            if (BH) u = pf2[j];
            else {
                u.x = h2u(__float22half2_rn(make_float2(pf[j].x, pf[j].y)));
                u.y = h2u(__float22half2_rn(make_float2(pf[j].z, pf[j].w)));
            }
            *(uint2*)(Bs0 + (kr + 8 * j) * NPADH + lc4) = u;
        }
    }
    __syncthreads();

    for (int i = 0; i < TOT; i++) {
        int tile = i / 3;
        int kc   = i - tile * 3;

        if (i + 1 < TOT) {
            int ntile = (i + 1) / 3;
            int nkc   = (i + 1) - ntile * 3;
            size_t src = bOff + (size_t)(nkc * 64 + kr) * HWN + nBase + ntile * 128 + lc4;
            if (BH) {
#pragma unroll
                for (int j = 0; j < 8; j++) pf2[j] = *(const uint2*)&Bh[src + (size_t)j * 8 * HWN];
            } else {
#pragma unroll
                for (int j = 0; j < 8; j++) pf[j] = *(const float4*)&Bf[src + (size_t)j * 8 * HWN];
            }
        }

        uint32_t sB = (i & 1) ? sB1 : sB0;
#pragma unroll
        for (int ks = 0; ks < 4; ks++) {
            uint32_t a[2][4];
            int kA = kc * 64 + ks * 16 + ((lane >> 4) << 3);
#pragma unroll
            for (int mt = 0; mt < 2; mt++) {
                int row = wm0 + mt * 16 + (lane & 15);
                LDSM_X4(a[mt], sA + (uint32_t)(row * KPADH + kA) * 2);
            }
#pragma unroll
            for (int pr = 0; pr < 4; pr++) {
                uint32_t bq[4];
                int brow = ks * 16 + (lane & 15);
                int bcol = wn0 + pr * 16 + ((lane >> 4) << 3);
                LDSM_X4_T(bq, sB + (uint32_t)(brow * NPADH + bcol) * 2);
                MMA_F16(c[0][2 * pr],     a[0], bq[0], bq[1]);
                MMA_F16(c[1][2 * pr],     a[1], bq[0], bq[1]);
                MMA_F16(c[0][2 * pr + 1], a[0], bq[2], bq[3]);
                MMA_F16(c[1][2 * pr + 1], a[1], bq[2], bq[3]);
            }
        }

        if (kc == 2) {
            int n0 = nBase + tile * 128;
#pragma unroll
            for (int mt = 0; mt < 2; mt++) {
                int row0 = m0 + wm0 + mt * 16 + g;
#pragma unroll
                for (int nt = 0; nt < 8; nt++) {
                    int col = n0 + wn0 + nt * 8 + 2 * t;
                    if (row0 < Mreal) {
                        if (OH) *(__half2*)&Ch[cOff + (size_t)row0 * HWN + col] =
                            __floats2half2_rn(c[mt][nt][0], c[mt][nt][1]);
                        else {
                            float2 v = {c[mt][nt][0], c[mt][nt][1]};
                            *(float2*)&Cf[cOff + (size_t)row0 * HWN + col] = v;
                        }
                    }
                    if (row0 + 8 < Mreal) {
                        if (OH) *(__half2*)&Ch[cOff + (size_t)(row0 + 8) * HWN + col] =
                            __floats2half2_rn(c[mt][nt][2], c[mt][nt][3]);
                        else {
                            float2 v = {c[mt][nt][2], c[mt][nt][3]};
                            *(float2*)&Cf[cOff + (size_t)(row0 + 8) * HWN + col] = v;
                        }
                    }
                    c[mt][nt][0] = 0.f; c[mt][nt][1] = 0.f;
                    c[mt][nt][2] = 0.f; c[mt][nt][3] = 0.f;
                }
            }
        }

        if (i + 1 < TOT) {
            __half* nbuf = (i & 1) ? Bs0 : Bs1;
#pragma unroll
            for (int j = 0; j < 8; j++) {
                uint2 u;
                if (BH) u = pf2[j];
                else {
                    u.x = h2u(__float22half2_rn(make_float2(pf[j].x, pf[j].y)));
                    u.y = h2u(__float22half2_rn(make_float2(pf[j].z, pf[j].w)));
                }
                *(uint2*)(nbuf + (kr + 8 * j) * NPADH + lc4) = u;
            }
            __syncthreads();
        }
    }
}

// ============================================================
// depthwise 3x3, fp16 in -> fp16 out, all 576 channels
// ============================================================
__global__ __launch_bounds__(256) void dwconv_all(
    const __half* __restrict__ in, const float* __restrict__ wAll,
    __half* __restrict__ out)
{
    int idx = blockIdx.x * 256 + threadIdx.x;
    int p4 = idx & 16383;
    int bc = idx >> 14;
    int ch = bc % OC3;
    int y  = p4 >> 6;
    int x0 = (p4 & 63) << 2;
    const __half* base = in + (size_t)bc * HWN;

    float w[9];
#pragma unroll
    for (int i = 0; i < 9; i++) w[i] = __ldg(&wAll[ch * 9 + i]);

    float s0 = 0.f, s1 = 0.f, s2 = 0.f, s3 = 0.f;
#pragma unroll
    for (int ky = 0; ky < 3; ky++) {
        int yy = y + ky - 1;
        if ((unsigned)yy >= 256u) continue;
        const __half* row = base + yy * 256;
        uint2 mid = *(const uint2*)&row[x0];
        __half2 m01 = *(__half2*)&mid.x;
        __half2 m23 = *(__half2*)&mid.y;
        float vx = __low2float(m01), vy = __high2float(m01);
        float vz = __low2float(m23), vw = __high2float(m23);
        float left  = (x0 > 0)   ? __half2float(row[x0 - 1]) : 0.f;
        float right = (x0 < 252) ? __half2float(row[x0 + 4]) : 0.f;
        float w0 = w[ky * 3], w1 = w[ky * 3 + 1], w2 = w[ky * 3 + 2];
        s0 += left * w0 + vx * w1 + vy * w2;
        s1 += vx * w0 + vy * w1 + vz * w2;
        s2 += vy * w0 + vz * w1 + vw * w2;
        s3 += vz * w0 + vw * w1 + right * w2;
    }
    uint2 u;
    u.x = h2u(__floats2half2_rn(s0, s1));
    u.y = h2u(__floats2half2_rn(s2, s3));
    *(uint2*)&out[(size_t)idx * 4] = u;
}

__global__ void zero_g48() {
    int i = blockIdx.x * blockDim.x + threadIdx.x;
    if (i < BATCH * NHEADS * 48 * 48) g_g48[i] = 0.f;
}

// ============================================================
// Tensor-core gram: per (b,h), S = [q;k] (48 x HWN) -> S S^T (48x48).
// 96 threads = 3 warps (m-tiles 0..2). Tile [48][64] fp16 in smem;
// A and B fragments from the same K-major tile (B via non-trans ldmatrix).
// ============================================================
#define GTPAD 72
__global__ __launch_bounds__(96) void gram_tc(const __half* __restrict__ chd, int pxPer)
{
    __shared__ __half sm[48][GTPAD];
    int bh = blockIdx.y;
    int b = bh >> 3, hh = bh & 7;
    int tid = threadIdx.x;
    int warp = tid >> 5, lane = tid & 31;
    int m0 = warp * 16;
    uint32_t sB = smem_u32(&sm[0][0]);

    float c[6][4];
#pragma unroll
    for (int nt = 0; nt < 6; nt++)
#pragma unroll
        for (int j = 0; j < 4; j++) c[nt][j] = 0.f;

    // ldmatrix addresses
    int aRow = m0 + (lane & 15);
    int aK   = (lane >> 4) << 3;
    uint32_t aAddr = sB + (uint32_t)(aRow * GTPAD + aK) * 2;
    int bRowLoc = ((lane >> 4) << 3) + (lane & 7);
    int bK      = ((lane >> 3) & 1) << 3;

    int nStart = blockIdx.x * pxPer;
    for (int n0 = nStart; n0 < nStart + pxPer; n0 += 64) {
        __syncthreads();
        for (int i = tid; i < 48 * 8; i += 96) {
            int row = i >> 3, seg = i & 7;
            int gch = (row < 24) ? (hh * HDIM + row) : (CDIM + hh * HDIM + (row - 24));
            *(uint4*)&sm[row][seg * 8] =
                *(const uint4*)&chd[((size_t)b * OC3 + gch) * HWN + n0 + seg * 8];
        }
        __syncthreads();
#pragma unroll
        for (int ks = 0; ks < 4; ks++) {
            uint32_t a[4];
            LDSM_X4(a, aAddr + (uint32_t)(ks * 16) * 2);
#pragma unroll
            for (int nb = 0; nb < 3; nb++) {
                uint32_t bq[4];
                int nr = nb * 16 + bRowLoc;
                LDSM_X4(bq, sB + (uint32_t)(nr * GTPAD + ks * 16 + bK) * 2);
                MMA_F16(c[2 * nb],     a, bq[0], bq[1]);
                MMA_F16(c[2 * nb + 1], a, bq[2], bq[3]);
            }
        }
    }

    float* gb = &g_g48[bh * 2304];
    int gm = lane >> 2, gt2 = (lane & 3) * 2;
#pragma unroll
    for (int nt = 0; nt < 6; nt++) {
        int col = nt * 8 + gt2;
        atomicAdd(&gb[(m0 + gm) * 48 + col],     c[nt][0]);
        atomicAdd(&gb[(m0 + gm) * 48 + col + 1], c[nt][1]);
        atomicAdd(&gb[(m0 + gm + 8) * 48 + col],     c[nt][2]);
        atomicAdd(&gb[(m0 + gm + 8) * 48 + col + 1], c[nt][3]);
    }
}

// ============================================================
// softmax + fold proj -> per-batch M (fp32)
// ============================================================
__global__ __launch_bounds__(256) void attn_proj_kernel(
    const float* __restrict__ projw, const float* __restrict__ temp)
{
    __shared__ float attn_s[NHEADS * HDIM * HDIM];
    int b = blockIdx.x;
    int t = threadIdx.x;
    if (t < CDIM) {
        int hh = t / HDIM, d = t % HDIM;
        const float* G = &g_g48[(b * NHEADS + hh) * 2304];
        float nq = fmaxf(sqrtf(G[d * 48 + d]), 1e-12f);
        float tm = temp[hh];
        float row[HDIM];
        float mx = -1e30f;
#pragma unroll
        for (int e = 0; e < HDIM; e++) {
            float nk = fmaxf(sqrtf(G[(24 + e) * 48 + 24 + e]), 1e-12f);
            float a = G[d * 48 + 24 + e] / (nq * nk) * tm;
            row[e] = a; mx = fmaxf(mx, a);
        }
        float s = 0.f;
#pragma unroll
        for (int e = 0; e < HDIM; e++) { row[e] = expf(row[e] - mx); s += row[e]; }
        float inv = 1.f / s;
#pragma unroll
        for (int e = 0; e < HDIM; e++) attn_s[hh * 576 + d * 24 + e] = row[e] * inv;
    }
    __syncthreads();
    if (t < CDIM) {
        int o = t;
        const float* pr = &projw[o * CDIM];
        for (int hh = 0; hh < NHEADS; hh++) {
#pragma unroll
            for (int e = 0; e < HDIM; e++) {
                float acc = 0.f;
#pragma unroll
                for (int d = 0; d < HDIM; d++)
                    acc += pr[hh * 24 + d] * attn_s[hh * 576 + d * 24 + e];
                g_M[((size_t)b * CDIM + o) * CDIM + hh * 24 + e] = acc;
            }
        }
    }
}

// ============================================================
extern "C" void kernel_launch(void* const* d_in, const int* in_sizes, int n_in,
                              void* d_out, int out_size)
{
    const float* x      = (const float*)d_in[0];
    const float* qkv_w  = (const float*)d_in[1];
    const float* dw_w   = (const float*)d_in[2];
    const float* proj_w = (const float*)d_in[3];
    const float* temp   = (const float*)d_in[4];
    float* out = (float*)d_out;

    __half *qkvh, *chd;
    float *Mp;
    cudaGetSymbolAddress((void**)&qkvh, g_qkvh);
    cudaGetSymbolAddress((void**)&chd,  g_ch);
    cudaGetSymbolAddress((void**)&Mp,   g_M);

    const int GEMM_SMEM = (128 * KPADH + 2 * 64 * NPADH) * 2;
    cudaFuncSetAttribute(gemm_f16<false, true>, cudaFuncAttributeMaxDynamicSharedMemorySize, GEMM_SMEM);
    cudaFuncSetAttribute(gemm_f16<true, false>, cudaFuncAttributeMaxDynamicSharedMemorySize, GEMM_SMEM);

    zero_g48<<<(BATCH * NHEADS * 2304 + 255) / 256, 256>>>();

    // K1: qkv = W_qkv @ x  (fp16 MMA, fp32 B in, fp16 C out)
    dim3 g1(5, HWN / (128 * NTILES), BATCH);
    gemm_f16<false, true><<<g1, 256, GEMM_SMEM>>>(qkv_w, 0, OC3,
                                                  x, (size_t)CDIM * HWN,
                                                  qkvh, (size_t)OC3 * HWN);

    // K2: depthwise 3x3, all channels, fp16->fp16
    dwconv_all<<<(BATCH * OC3 * HWN / 4) / 256, 256>>>(qkvh, dw_w, chd);

    // K3: tensor-core gram of [q;k]
    dim3 g3(64, BATCH * NHEADS);
    gram_tc<<<g3, 96>>>(chd, HWN / 64);

    // K4: softmax + fold proj
    attn_proj_kernel<<<BATCH, 256>>>(proj_w, temp);

    // K5: out = M_b @ v  (fp16 MMA, fp16 B in, fp32 C out)
    dim3 g5(2, HWN / (128 * NTILES), BATCH);
    gemm_f16<true, false><<<g5, 256, GEMM_SMEM>>>(Mp, (size_t)CDIM * CDIM, CDIM,
                                                  chd + (size_t)2 * CDIM * HWN, (size_t)OC3 * HWN,
                                                  out, (size_t)CDIM * HWN);
}

// round 9
// speedup vs baseline: 3.3627x; 1.0917x over previous
#include <cuda_runtime.h>
#include <cuda_fp16.h>
#include <stdint.h>
#include <math.h>

#define BATCH  4
#define CDIM   192
#define NHEADS 8
#define HDIM   24
#define HWN    65536
#define OC3    576
#define KDIM   192
#define NTILES 8
#define KPADH  200   // A row pad (halves)
#define NPADH  136   // B row pad (halves)

// ---- scratch (device globals) ----
__device__ __half g_qkvh[(size_t)BATCH * OC3 * HWN];  // 1x1-conv out, fp16
__device__ __half g_ch  [(size_t)BATCH * OC3 * HWN];  // dwconv out, fp16
__device__ float  g_g48 [BATCH * NHEADS * 48 * 48];   // [q;k] full gram
__device__ float  g_M   [BATCH * CDIM * CDIM];

__device__ __forceinline__ uint32_t smem_u32(const void* p) {
    uint32_t a;
    asm("{ .reg .u64 t; cvta.to.shared.u64 t, %1; cvt.u32.u64 %0, t; }" : "=r"(a) : "l"(p));
    return a;
}
__device__ __forceinline__ uint32_t h2u(__half2 h) { return *(uint32_t*)&h; }

#define LDSM_X4(r, addr) \
    asm volatile("ldmatrix.sync.aligned.m8n8.x4.shared.b16 {%0,%1,%2,%3}, [%4];" \
        : "=r"((r)[0]), "=r"((r)[1]), "=r"((r)[2]), "=r"((r)[3]) : "r"(addr))
#define LDSM_X4_T(r, addr) \
    asm volatile("ldmatrix.sync.aligned.m8n8.x4.trans.shared.b16 {%0,%1,%2,%3}, [%4];" \
        : "=r"((r)[0]), "=r"((r)[1]), "=r"((r)[2]), "=r"((r)[3]) : "r"(addr))
#define MMA_F16(cc, aa, b0, b1) \
    asm volatile("mma.sync.aligned.m16n8k16.row.col.f32.f16.f16.f32 " \
        "{%0,%1,%2,%3}, {%4,%5,%6,%7}, {%8,%9}, {%0,%1,%2,%3};" \
        : "+f"((cc)[0]), "+f"((cc)[1]), "+f"((cc)[2]), "+f"((cc)[3]) \
        : "r"((aa)[0]), "r"((aa)[1]), "r"((aa)[2]), "r"((aa)[3]), "r"(b0), "r"(b1))

// ============================================================
// fp16 HMMA GEMM: C[b][m][n] = sum_k A[b][m][k] * B[b][k][n]
// 128m x 128n CTA tile, K=192 (3 chunks of 64), double-buffered B,
// register prefetch. BH: B fp16 in gmem. OH: C stored fp16.
// ============================================================
template<bool BH, bool OH>
__global__ __launch_bounds__(256) void gemm_f16(
    const float* __restrict__ A, size_t aStride, int Mreal,
    const void* __restrict__ Bv, size_t bStride,
    void* __restrict__ C, size_t cStride)
{
    extern __shared__ __half hsm[];
    __half* As  = hsm;                       // [128][KPADH]
    __half* Bs0 = As + 128 * KPADH;          // [64][NPADH]
    __half* Bs1 = Bs0 + 64 * NPADH;

    const float*  Bf = (const float*)Bv;
    const __half* Bh = (const __half*)Bv;
    float*  Cf = (float*)C;
    __half* Ch = (__half*)C;

    int tid  = threadIdx.x;
    int warp = tid >> 5, lane = tid & 31;
    int g = lane >> 2, t = lane & 3;
    int wm0 = (warp >> 1) * 32;
    int wn0 = (warp & 1) * 64;

    int m0    = blockIdx.x * 128;
    int b     = blockIdx.z;
    int nBase = blockIdx.y * (128 * NTILES);
    const float* Ab = A + (size_t)b * aStride;
    size_t bOff = (size_t)b * bStride;
    size_t cOff = (size_t)b * cStride;

    for (int it = tid; it < 128 * 48; it += 256) {
        int row = it / 48, c4 = (it - row * 48) * 4;
        float4 v = make_float4(0.f, 0.f, 0.f, 0.f);
        if (m0 + row < Mreal) v = *(const float4*)&Ab[(size_t)(m0 + row) * KDIM + c4];
        uint2 u;
        u.x = h2u(__float22half2_rn(make_float2(v.x, v.y)));
        u.y = h2u(__float22half2_rn(make_float2(v.z, v.w)));
        *(uint2*)(As + row * KPADH + c4) = u;
    }

    int kr  = tid >> 5;
    int lc4 = lane * 4;
    float4 pf[8];
    uint2  pf2[8];

    float c[2][8][4];
#pragma unroll
    for (int mt = 0; mt < 2; mt++)
#pragma unroll
        for (int nt = 0; nt < 8; nt++)
#pragma unroll
            for (int j = 0; j < 4; j++) c[mt][nt][j] = 0.f;

    const int TOT = NTILES * 3;
    uint32_t sA  = smem_u32(As);
    uint32_t sB0 = smem_u32(Bs0);
    uint32_t sB1 = smem_u32(Bs1);

    {
        if (BH) {
#pragma unroll
            for (int j = 0; j < 8; j++)
                pf2[j] = *(const uint2*)&Bh[bOff + (size_t)(kr + 8 * j) * HWN + nBase + lc4];
        } else {
#pragma unroll
            for (int j = 0; j < 8; j++)
                pf[j] = *(const float4*)&Bf[bOff + (size_t)(kr + 8 * j) * HWN + nBase + lc4];
        }
#pragma unroll
        for (int j = 0; j < 8; j++) {
            uint2 u;
            if (BH) u = pf2[j];
            else {
                u.x = h2u(__float22half2_rn(make_float2(pf[j].x, pf[j].y)));
                u.y = h2u(__float22half2_rn(make_float2(pf[j].z, pf[j].w)));
            }
            *(uint2*)(Bs0 + (kr + 8 * j) * NPADH + lc4) = u;
        }
    }
    __syncthreads();

    for (int i = 0; i < TOT; i++) {
        int tile = i / 3;
        int kc   = i - tile * 3;

        if (i + 1 < TOT) {
            int ntile = (i + 1) / 3;
            int nkc   = (i + 1) - ntile * 3;
            size_t src = bOff + (size_t)(nkc * 64 + kr) * HWN + nBase + ntile * 128 + lc4;
            if (BH) {
#pragma unroll
                for (int j = 0; j < 8; j++) pf2[j] = *(const uint2*)&Bh[src + (size_t)j * 8 * HWN];
            } else {
#pragma unroll
                for (int j = 0; j < 8; j++) pf[j] = *(const float4*)&Bf[src + (size_t)j * 8 * HWN];
            }
        }

        uint32_t sB = (i & 1) ? sB1 : sB0;
#pragma unroll
        for (int ks = 0; ks < 4; ks++) {
            uint32_t a[2][4];
            int kA = kc * 64 + ks * 16 + ((lane >> 4) << 3);
#pragma unroll
            for (int mt = 0; mt < 2; mt++) {
                int row = wm0 + mt * 16 + (lane & 15);
                LDSM_X4(a[mt], sA + (uint32_t)(row * KPADH + kA) * 2);
            }
#pragma unroll
            for (int pr = 0; pr < 4; pr++) {
                uint32_t bq[4];
                int brow = ks * 16 + (lane & 15);
                int bcol = wn0 + pr * 16 + ((lane >> 4) << 3);
                LDSM_X4_T(bq, sB + (uint32_t)(brow * NPADH + bcol) * 2);
                MMA_F16(c[0][2 * pr],     a[0], bq[0], bq[1]);
                MMA_F16(c[1][2 * pr],     a[1], bq[0], bq[1]);
                MMA_F16(c[0][2 * pr + 1], a[0], bq[2], bq[3]);
                MMA_F16(c[1][2 * pr + 1], a[1], bq[2], bq[3]);
            }
        }

        if (kc == 2) {
            int n0 = nBase + tile * 128;
#pragma unroll
            for (int mt = 0; mt < 2; mt++) {
                int row0 = m0 + wm0 + mt * 16 + g;
#pragma unroll
                for (int nt = 0; nt < 8; nt++) {
                    int col = n0 + wn0 + nt * 8 + 2 * t;
                    if (row0 < Mreal) {
                        if (OH) *(__half2*)&Ch[cOff + (size_t)row0 * HWN + col] =
                            __floats2half2_rn(c[mt][nt][0], c[mt][nt][1]);
                        else {
                            float2 v = {c[mt][nt][0], c[mt][nt][1]};
                            *(float2*)&Cf[cOff + (size_t)row0 * HWN + col] = v;
                        }
                    }
                    if (row0 + 8 < Mreal) {
                        if (OH) *(__half2*)&Ch[cOff + (size_t)(row0 + 8) * HWN + col] =
                            __floats2half2_rn(c[mt][nt][2], c[mt][nt][3]);
                        else {
                            float2 v = {c[mt][nt][2], c[mt][nt][3]};
                            *(float2*)&Cf[cOff + (size_t)(row0 + 8) * HWN + col] = v;
                        }
                    }
                    c[mt][nt][0] = 0.f; c[mt][nt][1] = 0.f;
                    c[mt][nt][2] = 0.f; c[mt][nt][3] = 0.f;
                }
            }
        }

        if (i + 1 < TOT) {
            __half* nbuf = (i & 1) ? Bs0 : Bs1;
#pragma unroll
            for (int j = 0; j < 8; j++) {
                uint2 u;
                if (BH) u = pf2[j];
                else {
                    u.x = h2u(__float22half2_rn(make_float2(pf[j].x, pf[j].y)));
                    u.y = h2u(__float22half2_rn(make_float2(pf[j].z, pf[j].w)));
                }
                *(uint2*)(nbuf + (kr + 8 * j) * NPADH + lc4) = u;
            }
            __syncthreads();
        }
    }
}

// ============================================================
// depthwise 3x3, fp16 in -> fp16 out, 8 px per thread (deep MLP)
// ============================================================
__global__ __launch_bounds__(256) void dwconv_all(
    const __half* __restrict__ in, const float* __restrict__ wAll,
    __half* __restrict__ out)
{
    int idx = blockIdx.x * 256 + threadIdx.x;    // over BATCH*OC3*HWN/8
    int p8 = idx & 8191;
    int bc = idx >> 13;
    int ch = bc % OC3;
    int y  = p8 >> 5;
    int x0 = (p8 & 31) << 3;
    const __half* base = in + (size_t)bc * HWN;

    float w[9];
#pragma unroll
    for (int i = 0; i < 9; i++) w[i] = __ldg(&wAll[ch * 9 + i]);

    // gather all loads first (MLP)
    uint4 rowv[3];
    float lft[3], rgt[3];
    bool ok[3];
#pragma unroll
    for (int ky = 0; ky < 3; ky++) {
        int yy = y + ky - 1;
        ok[ky] = ((unsigned)yy < 256u);
        const __half* row = base + yy * 256;
        if (ok[ky]) {
            rowv[ky] = *(const uint4*)&row[x0];
            lft[ky]  = (x0 > 0)   ? __half2float(row[x0 - 1]) : 0.f;
            rgt[ky]  = (x0 < 248) ? __half2float(row[x0 + 8]) : 0.f;
        }
    }

    float s[8];
#pragma unroll
    for (int o = 0; o < 8; o++) s[o] = 0.f;

#pragma unroll
    for (int ky = 0; ky < 3; ky++) {
        if (!ok[ky]) continue;
        float f[10];
        const __half* hp = (const __half*)&rowv[ky];
        f[0] = lft[ky];
#pragma unroll
        for (int j = 0; j < 8; j++) f[j + 1] = __half2float(hp[j]);
        f[9] = rgt[ky];
        float w0 = w[ky * 3], w1 = w[ky * 3 + 1], w2 = w[ky * 3 + 2];
#pragma unroll
        for (int o = 0; o < 8; o++)
            s[o] += f[o] * w0 + f[o + 1] * w1 + f[o + 2] * w2;
    }

    uint4 u;
    u.x = h2u(__floats2half2_rn(s[0], s[1]));
    u.y = h2u(__floats2half2_rn(s[2], s[3]));
    u.z = h2u(__floats2half2_rn(s[4], s[5]));
    u.w = h2u(__floats2half2_rn(s[6], s[7]));
    *(uint4*)&out[(size_t)idx * 8] = u;
}

__global__ void zero_g48() {
    int i = blockIdx.x * blockDim.x + threadIdx.x;
    if (i < BATCH * NHEADS * 48 * 48) g_g48[i] = 0.f;
}

// ============================================================
// Tensor-core gram v2: per (b,h), S = [q;k] (48 x HWN) -> S S^T.
// 192 threads = 6 warps = 2 pixel-halves x 3 m-tiles. 128-px smem tile.
// ============================================================
#define GTPAD 136
__global__ __launch_bounds__(192) void gram_tc(const __half* __restrict__ chd, int pxPer)
{
    __shared__ __half sm[48][GTPAD];
    int bh = blockIdx.y;
    int b = bh >> 3, hh = bh & 7;
    int tid = threadIdx.x;
    int warp = tid >> 5, lane = tid & 31;
    int half = warp / 3;          // 0..1: which 64-px half
    int mt   = warp - half * 3;   // 0..2: m tile
    int m0 = mt * 16;
    int colBase = half * 64;
    uint32_t sB = smem_u32(&sm[0][0]);

    float c[6][4];
#pragma unroll
    for (int nt = 0; nt < 6; nt++)
#pragma unroll
        for (int j = 0; j < 4; j++) c[nt][j] = 0.f;

    int aRow = m0 + (lane & 15);
    int aK   = colBase + ((lane >> 4) << 3);
    uint32_t aAddr = sB + (uint32_t)(aRow * GTPAD + aK) * 2;
    int bRowLoc = ((lane >> 4) << 3) + (lane & 7);
    int bK      = colBase + (((lane >> 3) & 1) << 3);

    int nStart = blockIdx.x * pxPer;
    for (int n0 = nStart; n0 < nStart + pxPer; n0 += 128) {
        __syncthreads();
        for (int i = tid; i < 48 * 16; i += 192) {
            int row = i >> 4, seg = i & 15;
            int gch = (row < 24) ? (hh * HDIM + row) : (CDIM + hh * HDIM + (row - 24));
            *(uint4*)&sm[row][seg * 8] =
                *(const uint4*)&chd[((size_t)b * OC3 + gch) * HWN + n0 + seg * 8];
        }
        __syncthreads();
#pragma unroll
        for (int ks = 0; ks < 4; ks++) {
            uint32_t a[4];
            LDSM_X4(a, aAddr + (uint32_t)(ks * 16) * 2);
#pragma unroll
            for (int nb = 0; nb < 3; nb++) {
                uint32_t bq[4];
                int nr = nb * 16 + bRowLoc;
                LDSM_X4(bq, sB + (uint32_t)(nr * GTPAD + ks * 16 + bK) * 2);
                MMA_F16(c[2 * nb],     a, bq[0], bq[1]);
                MMA_F16(c[2 * nb + 1], a, bq[2], bq[3]);
            }
        }
    }

    float* gb = &g_g48[bh * 2304];
    int gm = lane >> 2, gt2 = (lane & 3) * 2;
#pragma unroll
    for (int nt = 0; nt < 6; nt++) {
        int col = nt * 8 + gt2;
        atomicAdd(&gb[(m0 + gm) * 48 + col],     c[nt][0]);
        atomicAdd(&gb[(m0 + gm) * 48 + col + 1], c[nt][1]);
        atomicAdd(&gb[(m0 + gm + 8) * 48 + col],     c[nt][2]);
        atomicAdd(&gb[(m0 + gm + 8) * 48 + col + 1], c[nt][3]);
    }
}

// ============================================================
// softmax + fold proj -> per-batch M (fp32)
// ============================================================
__global__ __launch_bounds__(256) void attn_proj_kernel(
    const float* __restrict__ projw, const float* __restrict__ temp)
{
    __shared__ float attn_s[NHEADS * HDIM * HDIM];
    int b = blockIdx.x;
    int t = threadIdx.x;
    if (t < CDIM) {
        int hh = t / HDIM, d = t % HDIM;
        const float* G = &g_g48[(b * NHEADS + hh) * 2304];
        float nq = fmaxf(sqrtf(G[d * 48 + d]), 1e-12f);
        float tm = temp[hh];
        float row[HDIM];
        float mx = -1e30f;
#pragma unroll
        for (int e = 0; e < HDIM; e++) {
            float nk = fmaxf(sqrtf(G[(24 + e) * 48 + 24 + e]), 1e-12f);
            float a = G[d * 48 + 24 + e] / (nq * nk) * tm;
            row[e] = a; mx = fmaxf(mx, a);
        }
        float s = 0.f;
#pragma unroll
        for (int e = 0; e < HDIM; e++) { row[e] = expf(row[e] - mx); s += row[e]; }
        float inv = 1.f / s;
#pragma unroll
        for (int e = 0; e < HDIM; e++) attn_s[hh * 576 + d * 24 + e] = row[e] * inv;
    }
    __syncthreads();
    if (t < CDIM) {
        int o = t;
        const float* pr = &projw[o * CDIM];
        for (int hh = 0; hh < NHEADS; hh++) {
#pragma unroll
            for (int e = 0; e < HDIM; e++) {
                float acc = 0.f;
#pragma unroll
                for (int d = 0; d < HDIM; d++)
                    acc += pr[hh * 24 + d] * attn_s[hh * 576 + d * 24 + e];
                g_M[((size_t)b * CDIM + o) * CDIM + hh * 24 + e] = acc;
            }
        }
    }
}

// ============================================================
extern "C" void kernel_launch(void* const* d_in, const int* in_sizes, int n_in,
                              void* d_out, int out_size)
{
    const float* x      = (const float*)d_in[0];
    const float* qkv_w  = (const float*)d_in[1];
    const float* dw_w   = (const float*)d_in[2];
    const float* proj_w = (const float*)d_in[3];
    const float* temp   = (const float*)d_in[4];
    float* out = (float*)d_out;

    __half *qkvh, *chd;
    float *Mp;
    cudaGetSymbolAddress((void**)&qkvh, g_qkvh);
    cudaGetSymbolAddress((void**)&chd,  g_ch);
    cudaGetSymbolAddress((void**)&Mp,   g_M);

    const int GEMM_SMEM = (128 * KPADH + 2 * 64 * NPADH) * 2;
    cudaFuncSetAttribute(gemm_f16<false, true>, cudaFuncAttributeMaxDynamicSharedMemorySize, GEMM_SMEM);
    cudaFuncSetAttribute(gemm_f16<true, false>, cudaFuncAttributeMaxDynamicSharedMemorySize, GEMM_SMEM);

    zero_g48<<<(BATCH * NHEADS * 2304 + 255) / 256, 256>>>();

    // K1: qkv = W_qkv @ x  (fp16 MMA, fp32 B in, fp16 C out)
    dim3 g1(5, HWN / (128 * NTILES), BATCH);
    gemm_f16<false, true><<<g1, 256, GEMM_SMEM>>>(qkv_w, 0, OC3,
                                                  x, (size_t)CDIM * HWN,
                                                  qkvh, (size_t)OC3 * HWN);

    // K2: depthwise 3x3, all channels, fp16->fp16, 8 px/thread
    dwconv_all<<<(BATCH * OC3 * HWN / 8) / 256, 256>>>(qkvh, dw_w, chd);

    // K3: tensor-core gram of [q;k], 128-px tiles
    dim3 g3(32, BATCH * NHEADS);
    gram_tc<<<g3, 192>>>(chd, HWN / 32);

    // K4: softmax + fold proj
    attn_proj_kernel<<<BATCH, 256>>>(proj_w, temp);

    // K5: out = M_b @ v  (fp16 MMA, fp16 B in, fp32 C out)
    dim3 g5(2, HWN / (128 * NTILES), BATCH);
    gemm_f16<true, false><<<g5, 256, GEMM_SMEM>>>(Mp, (size_t)CDIM * CDIM, CDIM,
                                                  chd + (size_t)2 * CDIM * HWN, (size_t)OC3 * HWN,
                                                  out, (size_t)CDIM * HWN);
}